// round 11
// baseline (speedup 1.0000x reference)
#include <cuda_runtime.h>

// ---------------------------------------------------------------------------
// JPEG 8x8 DCT-II + luminance quantization, fused.
//
// image:  [16, 1, 1024, 1024] f32
// qf:     [16] f32
// out:    [16, 64, 128, 128] f32   (channel = u*8 + v)
//
// R10: TWO threads per 8x8 block (lane l and l+16 of the same warp) to halve
// the register live set (64 -> 32 floats) and raise occupancy 24 -> ~36
// warps/SM. Lanes 0-15 hold rows 0-3 of 16 consecutive blocks; lanes 16-31
// hold rows 7,6,5,4 (reversed). Row DCT is per-thread; the column DCT's
// even/odd fold is one shfl.bfly(16) per value; low half then produces the
// even-frequency outputs (u=0,2,4,6), high half the odd ones (u=1,3,5,7).
// ---------------------------------------------------------------------------

// Butterfly coefficients (orthonormal DCT-II, a[k] folded in; a0=1/(2*sqrt2),
// a[k>0]=1/2). Literals round to the exact f32 values of the f64 reference.
#define A0f 0.35355339059327373f   /* a0 ; also a4*cos(pi/4) */
#define B1f 0.46193976625564337f   /* 0.5*cos(pi/8)   */
#define B3f 0.19134171618254492f   /* 0.5*cos(3pi/8)  */
#define G0f 0.49039264020161522f   /* 0.5*cos(pi/16)  */
#define G1f 0.41573480615127262f   /* 0.5*cos(3pi/16) */
#define G2f 0.27778511650980114f   /* 0.5*cos(5pi/16) */
#define G3f 0.09754516100806412f   /* 0.5*cos(7pi/16) */

// 8-point orthonormal DCT-II over a contiguous 8-float register row.
__device__ __forceinline__ void dct8_row(float* p)
{
    const float x0 = p[0], x1 = p[1], x2 = p[2], x3 = p[3];
    const float x4 = p[4], x5 = p[5], x6 = p[6], x7 = p[7];

    const float s0 = x0 + x7, s1 = x1 + x6, s2 = x2 + x5, s3 = x3 + x4;
    const float d0 = x0 - x7, d1 = x1 - x6, d2 = x2 - x5, d3 = x3 - x4;

    const float t0 = s0 + s3, t1 = s1 + s2;
    const float u0 = s0 - s3, u1 = s1 - s2;

    p[0] = A0f * (t0 + t1);
    p[4] = A0f * (t0 - t1);
    p[2] = fmaf(B3f, u1, B1f * u0);
    p[6] = fmaf(-B1f, u1, B3f * u0);

    p[1] = fmaf(G3f, d3, fmaf(G2f, d2, fmaf(G1f, d1, G0f * d0)));
    p[3] = fmaf(-G2f, d3, fmaf(-G0f, d2, fmaf(-G3f, d1, G1f * d0)));
    p[5] = fmaf( G1f, d3, fmaf( G3f, d2, fmaf(-G0f, d1, G2f * d0)));
    p[7] = fmaf(-G0f, d3, fmaf( G1f, d2, fmaf(-G2f, d1, G3f * d0)));
}

// INVQ[u][v] = 100 / Q[u][v]  (reference divides by Q/100; we multiply by 100/Q)
__device__ constexpr float INVQ[8][8] = {
    { 100.f/16.f, 100.f/11.f, 100.f/10.f, 100.f/16.f, 100.f/24.f, 100.f/40.f, 100.f/51.f,  100.f/61.f  },
    { 100.f/12.f, 100.f/12.f, 100.f/14.f, 100.f/19.f, 100.f/26.f, 100.f/58.f, 100.f/60.f,  100.f/55.f  },
    { 100.f/14.f, 100.f/13.f, 100.f/16.f, 100.f/24.f, 100.f/40.f, 100.f/57.f, 100.f/69.f,  100.f/56.f  },
    { 100.f/14.f, 100.f/17.f, 100.f/22.f, 100.f/29.f, 100.f/51.f, 100.f/87.f, 100.f/80.f,  100.f/62.f  },
    { 100.f/18.f, 100.f/22.f, 100.f/37.f, 100.f/56.f, 100.f/68.f, 100.f/109.f,100.f/103.f, 100.f/77.f  },
    { 100.f/24.f, 100.f/36.f, 100.f/55.f, 100.f/64.f, 100.f/81.f, 100.f/104.f,100.f/113.f, 100.f/92.f  },
    { 100.f/49.f, 100.f/64.f, 100.f/78.f, 100.f/87.f, 100.f/103.f,100.f/121.f,100.f/120.f, 100.f/101.f },
    { 100.f/72.f, 100.f/92.f, 100.f/95.f, 100.f/98.f, 100.f/112.f,100.f/100.f,100.f/103.f, 100.f/99.f  },
};

static constexpr int BATCH    = 16;
static constexpr int HEIGHT   = 1024;
static constexpr int WIDTH    = 1024;
static constexpr int NBI      = HEIGHT / 8;                 // 128
static constexpr int NBJ      = WIDTH / 8;                  // 128
static constexpr int NBLOCKS  = BATCH * NBI * NBJ;          // 262144
static constexpr int NTHREADS = NBLOCKS * 2;                // 524288
static constexpr int TPB      = 128;

__global__ void __launch_bounds__(TPB)
jpeg_dct_quant_kernel(const float* __restrict__ img,
                      const float* __restrict__ qf,
                      float* __restrict__ out)
{
    const int lane = threadIdx.x & 31;
    const int warp = (blockIdx.x * TPB + threadIdx.x) >> 5;
    const bool odd_half = lane >= 16;        // lanes 16-31: rows 7..4, odd u

    // 16 consecutive blocks per warp; half-warp lanes map to consecutive bj
    const int blk = (warp << 4) + (lane & 15);
    const int b   = blk >> 14;
    const int bi  = (blk >> 7) & 127;
    const int bj  = blk & 127;

    // ---- per-batch quality factor -> single reciprocal scale ----
    const float q      = qf[b];
    const float factor = (q < 50.0f) ? (5000.0f / q) : (200.0f - 2.0f * q);
    const float invF   = 1.0f / factor;
    const float negC   = -128.0f * invF;     // centering folded with invF

    // ---- load 4 rows (low half: rows 0..3; high half: rows 7,6,5,4) ----
    const float* src = img + ((size_t)b << 20) + ((size_t)(bi << 3) << 10) + (bj << 3);

    float x[4][8];
#pragma unroll
    for (int r = 0; r < 4; ++r) {
        const int row = odd_half ? (7 - r) : r;
        const float4 lo = *reinterpret_cast<const float4*>(src + ((size_t)row << 10));
        const float4 hi = *reinterpret_cast<const float4*>(src + ((size_t)row << 10) + 4);
        x[r][0] = fmaf(lo.x, invF, negC); x[r][1] = fmaf(lo.y, invF, negC);
        x[r][2] = fmaf(lo.z, invF, negC); x[r][3] = fmaf(lo.w, invF, negC);
        x[r][4] = fmaf(hi.x, invF, negC); x[r][5] = fmaf(hi.y, invF, negC);
        x[r][6] = fmaf(hi.z, invF, negC); x[r][7] = fmaf(hi.w, invF, negC);
    }

    // ---- row DCT (each thread owns complete 8-wide rows) ----
#pragma unroll
    for (int r = 0; r < 4; ++r)
        dct8_row(&x[r][0]);

    // ---- column fold via bfly(16): low half gets s_n = x_n + x_{7-n},
    //      high half gets d_n = x_n - x_{7-n}.  (sgn*own + recv, sgn = +/-1)
    const float sgn = odd_half ? -1.0f : 1.0f;
#pragma unroll
    for (int n = 0; n < 4; ++n) {
#pragma unroll
        for (int c = 0; c < 8; ++c) {
            const float recv = __shfl_xor_sync(0xffffffffu, x[n][c], 16);
            x[n][c] = fmaf(x[n][c], sgn, recv);
        }
    }

    // ---- second stage + quantize + store ----
    // out[b][u*8+v][bi][bj]; channel stride = 128*128 = 16384 elements.
    float* dst = out + ((size_t)b << 20) + (bi << 7) + bj;

    if (!odd_half) {
        // even-frequency outputs u = 0, 2, 4, 6 from s0..s3
#pragma unroll
        for (int c = 0; c < 8; ++c) {
            const float s0 = x[0][c], s1 = x[1][c], s2 = x[2][c], s3 = x[3][c];
            const float t0 = s0 + s3, t1 = s1 + s2;
            const float u0 = s0 - s3, u1 = s1 - s2;
            const float o0 = A0f * (t0 + t1);
            const float o4 = A0f * (t0 - t1);
            const float o2 = fmaf(B3f, u1, B1f * u0);
            const float o6 = fmaf(-B1f, u1, B3f * u0);
            __stcs(&dst[(size_t)((0 << 3) + c) << 14], o0 * INVQ[0][c]);
            __stcs(&dst[(size_t)((2 << 3) + c) << 14], o2 * INVQ[2][c]);
            __stcs(&dst[(size_t)((4 << 3) + c) << 14], o4 * INVQ[4][c]);
            __stcs(&dst[(size_t)((6 << 3) + c) << 14], o6 * INVQ[6][c]);
        }
    } else {
        // odd-frequency outputs u = 1, 3, 5, 7 from d0..d3
#pragma unroll
        for (int c = 0; c < 8; ++c) {
            const float d0 = x[0][c], d1 = x[1][c], d2 = x[2][c], d3 = x[3][c];
            const float o1 = fmaf(G3f, d3, fmaf(G2f, d2, fmaf(G1f, d1, G0f * d0)));
            const float o3 = fmaf(-G2f, d3, fmaf(-G0f, d2, fmaf(-G3f, d1, G1f * d0)));
            const float o5 = fmaf( G1f, d3, fmaf( G3f, d2, fmaf(-G0f, d1, G2f * d0)));
            const float o7 = fmaf(-G0f, d3, fmaf( G1f, d2, fmaf(-G2f, d1, G3f * d0)));
            __stcs(&dst[(size_t)((1 << 3) + c) << 14], o1 * INVQ[1][c]);
            __stcs(&dst[(size_t)((3 << 3) + c) << 14], o3 * INVQ[3][c]);
            __stcs(&dst[(size_t)((5 << 3) + c) << 14], o5 * INVQ[5][c]);
            __stcs(&dst[(size_t)((7 << 3) + c) << 14], o7 * INVQ[7][c]);
        }
    }
}

extern "C" void kernel_launch(void* const* d_in, const int* in_sizes, int n_in,
                              void* d_out, int out_size)
{
    (void)in_sizes; (void)n_in; (void)out_size;
    const float* img = (const float*)d_in[0];
    const float* qf  = (const float*)d_in[1];
    float*       out = (float*)d_out;

    jpeg_dct_quant_kernel<<<NTHREADS / TPB, TPB>>>(img, qf, out);
}